// round 7
// baseline (speedup 1.0000x reference)
#include <cuda_runtime.h>
#include <cuda_bf16.h>
#include <math.h>
#include <stdint.h>

// ======================= constants =======================
#define NBLOCKS   512          // CTAs, 64 rays each
#define RAYS      64
#define NTH       512
#define HID       256

#define EPS      1e-3f
#define MAX_RAY  3.5f
#define SPHERE_R 0.7f
#define SCALE_TR 1.41421356237309515f
#define COS30    0.8660254037844387f

// ======================= smem layout (bytes) =======================
// A planes: blocked tiles: byte = ((k>>3)*8 + (r>>3))*128 + (r&7)*16 + (k&7)*2
#define SM_A1    0          // 32768
#define SM_A2    32768      // 32768
#define SM_A3    65536      // 32768
#define SM_B     98304      // 2 bufs x 49152 (plane1 16384 | plane2 16384 | plane3 16384)
#define SM_W1R   196608     // 3*256 f
#define SM_C1    199680     // 256 f
#define SM_BW    200704     // 128 float4 {b2[2i],b2[2i+1],w3[2i],w3[2i+1]}
#define SM_POS   202752     // 64*3 f
#define SM_DIR   203520     // 64*3 f
#define SM_T     204288     // 64 f
#define SM_ACT   204544     // 64 i
#define SM_PS    204800     // 4*64 f
#define SMEM_TOTAL 205824

// ======================= PTX helpers (baseline ISA only) =======================
__device__ __forceinline__ uint32_t smem_u32(const void* p) {
    uint32_t a;
    asm("{ .reg .u64 t; cvta.to.shared.u64 t, %1; cvt.u32.u64 %0, t; }" : "=r"(a) : "l"(p));
    return a;
}
#define LDSM4(r, addr) \
    asm volatile("ldmatrix.sync.aligned.m8n8.x4.shared.b16 {%0,%1,%2,%3}, [%4];" \
        : "=r"((r)[0]), "=r"((r)[1]), "=r"((r)[2]), "=r"((r)[3]) : "r"(addr))

#define MMA16816(d, a, b0, b1) \
    asm volatile("mma.sync.aligned.m16n8k16.row.col.f32.bf16.bf16.f32 " \
        "{%0,%1,%2,%3}, {%4,%5,%6,%7}, {%8,%9}, {%0,%1,%2,%3};" \
        : "+f"((d)[0]), "+f"((d)[1]), "+f"((d)[2]), "+f"((d)[3]) \
        : "r"((a)[0]), "r"((a)[1]), "r"((a)[2]), "r"((a)[3]), "r"(b0), "r"(b1))

#define CP16(daddr, sptr) \
    asm volatile("cp.async.cg.shared.global [%0], [%1], 16;" :: "r"(daddr), "l"(sptr) : "memory")
#define CP_COMMIT() asm volatile("cp.async.commit_group;" ::: "memory")
#define CP_WAIT0()  asm volatile("cp.async.wait_group 0;" ::: "memory")

// 3-way bf16 split: v = s1 + s2 + s3 + eps, |eps| <= 2^-27 |v|
__device__ __forceinline__ void split3(float v, __nv_bfloat16& s1, __nv_bfloat16& s2, __nv_bfloat16& s3) {
    s1 = __float2bfloat16_rn(v);
    float r1 = v - __bfloat162float(s1);
    s2 = __float2bfloat16_rn(r1);
    float r2 = r1 - __bfloat162float(s2);
    s3 = __float2bfloat16_rn(r2);
}
__device__ __forceinline__ uint32_t pack2(__nv_bfloat16 e, __nv_bfloat16 o) {
    return (uint32_t)__bfloat16_as_ushort(e) | ((uint32_t)__bfloat16_as_ushort(o) << 16);
}

// ======================= device globals =======================
__device__ float g_c1[HID];
// W2^T split to 3 bf16 planes, chunk-blocked for ldmatrix:
// chunk c (k in [c*32,(c+1)*32)): u32 idx = ((kc>>3)*32 + (n>>3))*32 + (n&7)*4 + ((kc&7)>>1)
__device__ uint4 g_B1[8][1024];
__device__ uint4 g_B2[8][1024];
__device__ uint4 g_B3[8][1024];

// ======================= prep kernels =======================
__global__ void prep_c1_kernel(const float* __restrict__ lat_geo,
                               const float* __restrict__ lat_exp,
                               const float* __restrict__ lat_app,
                               const float* __restrict__ W1,
                               const float* __restrict__ b1) {
    __shared__ float lat[484];
    int tid = threadIdx.x;
    if (tid < 256) lat[tid] = lat_geo[tid];
    if (tid < 100) lat[256 + tid] = lat_exp[tid];
    if (tid < 128) lat[356 + tid] = lat_app[tid];
    __syncthreads();
    float c = b1[tid];
#pragma unroll 4
    for (int i = 0; i < 484; i++) c = fmaf(lat[i], W1[(3 + i) * 256 + tid], c);
    g_c1[tid] = c;
}

__global__ void prep_w2_kernel(const float* __restrict__ W2) {
    int idx = blockIdx.x * blockDim.x + threadIdx.x;   // 32768 = 256 n x 128 kpairs
    if (idx >= 256 * 128) return;
    int n = idx >> 7, kp = idx & 127;
    int k = 2 * kp;
    float v0 = W2[k * 256 + n];
    float v1 = W2[(k + 1) * 256 + n];
    __nv_bfloat16 p0, q0, r0, p1, q1, r1;
    split3(v0, p0, q0, r0);
    split3(v1, p1, q1, r1);
    int c = k >> 5, kc = k & 31;
    int u = ((kc >> 3) * 32 + (n >> 3)) * 32 + (n & 7) * 4 + ((kc & 7) >> 1);
    ((uint32_t*)g_B1)[c * 4096 + u] = pack2(p0, p1);
    ((uint32_t*)g_B2)[c * 4096 + u] = pack2(q0, q1);
    ((uint32_t*)g_B3)[c * 4096 + u] = pack2(r0, r1);
}

// ======================= persistent eval kernel =======================
__global__ void __launch_bounds__(NTH, 1)
eval_all_kernel(const float* __restrict__ W1,
                const float* __restrict__ b2,
                const float* __restrict__ W3,
                const float* __restrict__ b3,
                float* __restrict__ out) {
    extern __shared__ char smem[];
    const uint32_t sb = smem_u32(smem);
    float*  w1r  = (float*)(smem + SM_W1R);
    float*  c1s  = (float*)(smem + SM_C1);
    float4* bwS  = (float4*)(smem + SM_BW);
    float*  posS = (float*)(smem + SM_POS);
    float*  dirS = (float*)(smem + SM_DIR);
    float*  tS   = (float*)(smem + SM_T);
    int*    actS = (int*)  (smem + SM_ACT);
    float*  pS   = (float*)(smem + SM_PS);

    const int tid  = threadIdx.x;
    const int lane = tid & 31;
    const int wid  = tid >> 5;     // 0..15
    const int rg   = wid & 3;      // row group: rays [rg*16, rg*16+16)
    const int cg   = wid >> 2;     // col group: cols [cg*64, cg*64+64)
    const int grp  = lane >> 3;    // ldmatrix quad
    const float b3v = b3[0];

    // ---- stage constants ----
    if (tid < 256) {
        w1r[tid]       = W1[tid];
        w1r[256 + tid] = W1[256 + tid];
        w1r[512 + tid] = W1[512 + tid];
        c1s[tid] = g_c1[tid];
    }
    if (tid < 128) {
        float4 bw;
        bw.x = b2[2 * tid]; bw.y = b2[2 * tid + 1];
        bw.z = W3[(2 * tid) * 4]; bw.w = W3[(2 * tid + 1) * 4];
        bwS[tid] = bw;
    }
    // ---- ray init ----
    if (tid < RAYS) {
        int rgid = blockIdx.x * RAYS + tid;
        int view = rgid >> 14;
        int p = rgid & 16383;
        int i = p >> 7, j = p & 127;
        float u = (i + 0.5f) * (1.0f / 128.0f) - 0.5f;
        float v = 0.5f - (j + 0.5f) * (1.0f / 128.0f);
        float dx = u, dy = v, dz = -1.0f;
        float inv = 1.0f / sqrtf(dx * dx + dy * dy + dz * dz);
        dx *= inv; dy *= inv; dz *= inv;
        float s = view ? 0.5f : -0.5f;
        const float c = COS30;
        float rx = c * dx + s * dz;
        float ry = dy;
        float rz = -s * dx + c * dz;
        posS[tid * 3 + 0] = 2.2f * s + 2.2f * rx;
        posS[tid * 3 + 1] = 2.2f * ry;
        posS[tid * 3 + 2] = 2.2f * c + 2.2f * rz;
        dirS[tid * 3 + 0] = rx;
        dirS[tid * 3 + 1] = ry;
        dirS[tid * 3 + 2] = rz;
        tS[tid] = 0.0f;
        actS[tid] = 1;
    }
    __syncthreads();

    // per-thread invariant ldmatrix offsets
    // A tile idx = kb*8 + rb (128B tiles); rb = rg*2 + (grp&1); kb-part from grp>>1
    const uint32_t aOff = (uint32_t)((rg * 2 + (grp & 1)) * 128 + (lane & 7) * 16 + (grp >> 1) * 1024);
    // B tile idx = kb*32 + nb; nb = cg*8 + (grp&1) (+2 per p); kb-part from grp>>1
    const uint32_t bOff = (uint32_t)((cg * 8 + (grp & 1)) * 128 + (lane & 7) * 16 + (grp >> 1) * 4096);

    bool skip = false;

    // ================= 7 sequential SDF evals =================
    for (int e = 0; e < 7; e++) {
        if (skip && e < 6) continue;   // exact: all rays inactive -> no state change

        // ---- prefetch B chunk 0 (3 planes) into buf 0 ----
        {
            uint32_t d = sb + SM_B;
#pragma unroll
            for (int t = 0; t < 2; t++) {
                int i = tid + t * 512;
                CP16(d + (uint32_t)(i * 16),          &g_B1[0][i]);
                CP16(d + 16384u + (uint32_t)(i * 16), &g_B2[0][i]);
                CP16(d + 32768u + (uint32_t)(i * 16), &g_B3[0][i]);
            }
            CP_COMMIT();
        }

        // ---- GEMM1: h1 = relu(pos@W1 + c1), 3-way split -> A planes ----
        {
            const int ray = tid >> 3;     // 8 threads per ray
            const int kq  = tid & 7;      // k in [kq*32, kq*32+32)
            const float px = posS[ray * 3 + 0];
            const float py = posS[ray * 3 + 1];
            const float pz = posS[ray * 3 + 2];
            uint32_t* a1 = (uint32_t*)(smem + SM_A1);
            uint32_t* a2 = (uint32_t*)(smem + SM_A2);
            uint32_t* a3 = (uint32_t*)(smem + SM_A3);
#pragma unroll 4
            for (int j = 0; j < 16; j++) {
                int k0 = kq * 32 + 2 * j;
                float2 wx = *(const float2*)&w1r[k0];
                float2 wy = *(const float2*)&w1r[256 + k0];
                float2 wz = *(const float2*)&w1r[512 + k0];
                float2 cc = *(const float2*)&c1s[k0];
                float h0 = fmaxf(fmaf(px, wx.x, fmaf(py, wy.x, fmaf(pz, wz.x, cc.x))), 0.0f);
                float h1 = fmaxf(fmaf(px, wx.y, fmaf(py, wy.y, fmaf(pz, wz.y, cc.y))), 0.0f);
                __nv_bfloat16 p0, q0, r0, p1, q1, r1;
                split3(h0, p0, q0, r0);
                split3(h1, p1, q1, r1);
                int u = ((k0 >> 3) * 8 + (ray >> 3)) * 32 + (ray & 7) * 4 + ((k0 & 7) >> 1);
                a1[u] = pack2(p0, p1);
                a2[u] = pack2(q0, q1);
                a3[u] = pack2(r0, r1);
            }
        }

        // ---- GEMM2 k-loop: 8 chunks of K=32, double-buffered, 6-term split ----
        float acc[8][4];
#pragma unroll
        for (int i = 0; i < 8; i++)
#pragma unroll
            for (int j = 0; j < 4; j++) acc[i][j] = 0.0f;

        for (int c = 0; c < 8; c++) {
            CP_WAIT0();
            __syncthreads();   // chunk c visible; A visible (c==0); buf (c+1)&1 free

            if (c < 7) {
                uint32_t d = sb + SM_B + (uint32_t)(((c + 1) & 1) * 49152);
#pragma unroll
                for (int t = 0; t < 2; t++) {
                    int i = tid + t * 512;
                    CP16(d + (uint32_t)(i * 16),          &g_B1[c + 1][i]);
                    CP16(d + 16384u + (uint32_t)(i * 16), &g_B2[c + 1][i]);
                    CP16(d + 32768u + (uint32_t)(i * 16), &g_B3[c + 1][i]);
                }
                CP_COMMIT();
            }

            const uint32_t bufb = sb + SM_B + (uint32_t)((c & 1) * 49152);
            const uint32_t aCh  = sb + (uint32_t)(c * 4096);
#pragma unroll
            for (int s = 0; s < 2; s++) {
                uint32_t a1f[4], a2f[4], a3f[4];
                LDSM4(a1f, aCh + SM_A1 + (uint32_t)(s * 2048) + aOff);
                LDSM4(a2f, aCh + SM_A2 + (uint32_t)(s * 2048) + aOff);
                LDSM4(a3f, aCh + SM_A3 + (uint32_t)(s * 2048) + aOff);
                const uint32_t bB = bufb + (uint32_t)(s * 8192) + bOff;
#pragma unroll
                for (int p = 0; p < 4; p++) {
                    uint32_t b1f[4], b2f[4], b3f[4];
                    LDSM4(b1f, bB + (uint32_t)(p * 256));
                    LDSM4(b2f, bB + 16384u + (uint32_t)(p * 256));
                    LDSM4(b3f, bB + 32768u + (uint32_t)(p * 256));
                    float* c0 = acc[p * 2 + 0];
                    float* c1 = acc[p * 2 + 1];
                    MMA16816(c0, a1f, b1f[0], b1f[2]);   // a1*b1
                    MMA16816(c1, a1f, b1f[1], b1f[3]);
                    MMA16816(c0, a1f, b2f[0], b2f[2]);   // a1*b2
                    MMA16816(c1, a1f, b2f[1], b2f[3]);
                    MMA16816(c0, a2f, b1f[0], b1f[2]);   // a2*b1
                    MMA16816(c1, a2f, b1f[1], b1f[3]);
                    MMA16816(c0, a2f, b2f[0], b2f[2]);   // a2*b2
                    MMA16816(c1, a2f, b2f[1], b2f[3]);
                    MMA16816(c0, a1f, b3f[0], b3f[2]);   // a1*b3
                    MMA16816(c1, a1f, b3f[1], b3f[3]);
                    MMA16816(c0, a3f, b1f[0], b1f[2]);   // a3*b1
                    MMA16816(c1, a3f, b1f[1], b1f[3]);
                }
            }
        }

        // ---- epilogue: h2 = relu(acc + b2); partial p = h2 . w3 ----
        {
            float p0 = 0.0f, p1 = 0.0f;   // rows rg*16+(lane>>2) and +8
#pragma unroll
            for (int nt = 0; nt < 8; nt++) {
                int n0 = cg * 64 + nt * 8 + (lane & 3) * 2;
                float4 bw = bwS[n0 >> 1];
                p0 += fmaxf(acc[nt][0] + bw.x, 0.0f) * bw.z
                    + fmaxf(acc[nt][1] + bw.y, 0.0f) * bw.w;
                p1 += fmaxf(acc[nt][2] + bw.x, 0.0f) * bw.z
                    + fmaxf(acc[nt][3] + bw.y, 0.0f) * bw.w;
            }
            p0 += __shfl_xor_sync(0xFFFFFFFFu, p0, 1);
            p0 += __shfl_xor_sync(0xFFFFFFFFu, p0, 2);
            p1 += __shfl_xor_sync(0xFFFFFFFFu, p1, 1);
            p1 += __shfl_xor_sync(0xFFFFFFFFu, p1, 2);
            if ((lane & 3) == 0) {
                int r = rg * 16 + (lane >> 2);
                pS[cg * 64 + r]     = p0;
                pS[cg * 64 + r + 8] = p1;
            }
        }
        __syncthreads();

        // ---- per-ray trace update / final output ----
        int rayLive = 0;
        if (tid < RAYS) {
            float p = pS[tid] + pS[64 + tid] + pS[128 + tid] + pS[192 + tid];
            float px = posS[tid * 3 + 0];
            float py = posS[tid * 3 + 1];
            float pz = posS[tid * 3 + 2];
            float d = sqrtf(px * px + py * py + pz * pz) - SPHERE_R + (p + b3v);
            bool hit = fabsf(d) < EPS;
            if (e == 6) {
                int ray = blockIdx.x * RAYS + tid;
                out[ray * 3 + 0] = hit ? px : 0.0f;
                out[ray * 3 + 1] = hit ? py : 0.0f;
                out[ray * 3 + 2] = hit ? pz : 0.0f;
            } else {
                int act = actS[tid];
                float adv = (act && !hit) ? SCALE_TR * d : 0.0f;
                posS[tid * 3 + 0] = fmaf(adv, dirS[tid * 3 + 0], px);
                posS[tid * 3 + 1] = fmaf(adv, dirS[tid * 3 + 1], py);
                posS[tid * 3 + 2] = fmaf(adv, dirS[tid * 3 + 2], pz);
                float tt = tS[tid] + adv;
                tS[tid] = tt;
                rayLive = (act && !hit && (tt < MAX_RAY)) ? 1 : 0;
                actS[tid] = rayLive;
            }
        }
        // block-wide active count (also serves as the eval-boundary barrier)
        int nAlive = __syncthreads_count(rayLive);
        if (e < 6) skip = (nAlive == 0);
    }
}

// ======================= launch =======================
extern "C" void kernel_launch(void* const* d_in, const int* in_sizes, int n_in,
                              void* d_out, int out_size) {
    const float* lat_geo = (const float*)d_in[0];
    const float* lat_exp = (const float*)d_in[1];
    const float* lat_app = (const float*)d_in[2];
    const float* W1      = (const float*)d_in[3];
    const float* b1      = (const float*)d_in[4];
    const float* W2      = (const float*)d_in[5];
    const float* b2      = (const float*)d_in[6];
    const float* W3      = (const float*)d_in[7];
    const float* b3      = (const float*)d_in[8];
    float* out = (float*)d_out;

    cudaFuncSetAttribute(eval_all_kernel,
                         cudaFuncAttributeMaxDynamicSharedMemorySize, SMEM_TOTAL);

    prep_c1_kernel<<<1, 256>>>(lat_geo, lat_exp, lat_app, W1, b1);
    prep_w2_kernel<<<128, 256>>>(W2);
    eval_all_kernel<<<NBLOCKS, NTH, SMEM_TOTAL>>>(W1, b2, W3, b3, out);
}

// round 16
// speedup vs baseline: 1.0922x; 1.0922x over previous
#include <cuda_runtime.h>
#include <cuda_bf16.h>
#include <math.h>
#include <stdint.h>

// ======================= constants =======================
#define NBLOCKS   512          // CTAs, 64 rays each
#define RAYS      64
#define NTH       512
#define HID       256

#define EPS      1e-3f
#define MAX_RAY  3.5f
#define SPHERE_R 0.7f
#define SCALE_TR 1.41421356237309515f
#define COS30    0.8660254037844387f

// ======================= smem layout (bytes) =======================
// A planes: blocked tiles: byte = ((k>>3)*8 + (r>>3))*128 + (r&7)*16 + (k&7)*2
#define SM_A1    0          // 32768
#define SM_A2    32768      // 32768
#define SM_A3    65536      // 32768
#define SM_B     98304      // 2 bufs x 49152 (plane1 | plane2 | plane3)
#define SM_W1R   196608     // 3*256 f
#define SM_C1    199680     // 256 f
#define SM_BW    200704     // 128 float4 {b2[2i],b2[2i+1],w3[2i],w3[2i+1]}
#define SM_POS   202752     // 64*3 f
#define SM_DIR   203520     // 64*3 f
#define SM_T     204288     // 64 f
#define SM_ST    204544     // 64 i  (0=done,1=active,2=need-final)
#define SM_PS    204800     // 4*64 f
#define SM_PERM  205824     // 64 i
#define SM_ROWOF 206080     // 64 i
#define SM_DFIN  206336     // 64 f
#define SM_CNT   206592     // 4 i
#define SMEM_TOTAL 206848

// ======================= PTX helpers (baseline ISA only) =======================
__device__ __forceinline__ uint32_t smem_u32(const void* p) {
    uint32_t a;
    asm("{ .reg .u64 t; cvta.to.shared.u64 t, %1; cvt.u32.u64 %0, t; }" : "=r"(a) : "l"(p));
    return a;
}
#define LDSM4(r, addr) \
    asm volatile("ldmatrix.sync.aligned.m8n8.x4.shared.b16 {%0,%1,%2,%3}, [%4];" \
        : "=r"((r)[0]), "=r"((r)[1]), "=r"((r)[2]), "=r"((r)[3]) : "r"(addr))

#define MMA16816(d, a, b0, b1) \
    asm volatile("mma.sync.aligned.m16n8k16.row.col.f32.bf16.bf16.f32 " \
        "{%0,%1,%2,%3}, {%4,%5,%6,%7}, {%8,%9}, {%0,%1,%2,%3};" \
        : "+f"((d)[0]), "+f"((d)[1]), "+f"((d)[2]), "+f"((d)[3]) \
        : "r"((a)[0]), "r"((a)[1]), "r"((a)[2]), "r"((a)[3]), "r"(b0), "r"(b1))

#define CP16(daddr, sptr) \
    asm volatile("cp.async.cg.shared.global [%0], [%1], 16;" :: "r"(daddr), "l"(sptr) : "memory")
#define CP_COMMIT() asm volatile("cp.async.commit_group;" ::: "memory")
#define CP_WAIT0()  asm volatile("cp.async.wait_group 0;" ::: "memory")

// 3-way bf16 split: v = s1 + s2 + s3 + eps, |eps| <= 2^-27 |v|
__device__ __forceinline__ void split3(float v, __nv_bfloat16& s1, __nv_bfloat16& s2, __nv_bfloat16& s3) {
    s1 = __float2bfloat16_rn(v);
    float r1 = v - __bfloat162float(s1);
    s2 = __float2bfloat16_rn(r1);
    float r2 = r1 - __bfloat162float(s2);
    s3 = __float2bfloat16_rn(r2);
}
__device__ __forceinline__ uint32_t pack2(__nv_bfloat16 e, __nv_bfloat16 o) {
    return (uint32_t)__bfloat16_as_ushort(e) | ((uint32_t)__bfloat16_as_ushort(o) << 16);
}

// ======================= device globals =======================
__device__ float g_c1[HID];
// W2^T split to 3 bf16 planes, chunk-blocked for ldmatrix:
// chunk c (k in [c*32,(c+1)*32)): u32 idx = ((kc>>3)*32 + (n>>3))*32 + (n&7)*4 + ((kc&7)>>1)
__device__ uint4 g_B1[8][1024];
__device__ uint4 g_B2[8][1024];
__device__ uint4 g_B3[8][1024];

// ======================= prep kernels =======================
// 1024 threads: 0-255 run the EXACT same fma chain as before (bit-identical c1);
// 256-1023 prefetch W1 into L2 to kill the DRAM-latency serialization.
__global__ void prep_c1_kernel(const float* __restrict__ lat_geo,
                               const float* __restrict__ lat_exp,
                               const float* __restrict__ lat_app,
                               const float* __restrict__ W1,
                               const float* __restrict__ b1) {
    __shared__ float lat[484];
    int tid = threadIdx.x;
    if (tid < 256) lat[tid] = lat_geo[tid];
    else if (tid < 356) lat[tid] = lat_exp[tid - 256];
    else if (tid < 484) lat[tid] = lat_app[tid - 356];
    __syncthreads();
    if (tid >= 256) {
        // prefetch W1 rows 3..486 (484*256 floats) into L2, 128B granularity
        const char* base = (const char*)(W1 + 3 * 256);
        for (long off = (long)(tid - 256) * 128; off < 484L * 256 * 4; off += 768L * 128)
            asm volatile("prefetch.global.L2 [%0];" :: "l"(base + off));
        return;
    }
    float c = b1[tid];
#pragma unroll 16
    for (int i = 0; i < 484; i++) c = fmaf(lat[i], W1[(3 + i) * 256 + tid], c);
    g_c1[tid] = c;
}

__global__ void prep_w2_kernel(const float* __restrict__ W2) {
    int idx = blockIdx.x * blockDim.x + threadIdx.x;   // 32768 = 256 n x 128 kpairs
    if (idx >= 256 * 128) return;
    int n = idx >> 7, kp = idx & 127;
    int k = 2 * kp;
    float v0 = W2[k * 256 + n];
    float v1 = W2[(k + 1) * 256 + n];
    __nv_bfloat16 p0, q0, r0, p1, q1, r1;
    split3(v0, p0, q0, r0);
    split3(v1, p1, q1, r1);
    int c = k >> 5, kc = k & 31;
    int u = ((kc >> 3) * 32 + (n >> 3)) * 32 + (n & 7) * 4 + ((kc & 7) >> 1);
    ((uint32_t*)g_B1)[c * 4096 + u] = pack2(p0, p1);
    ((uint32_t*)g_B2)[c * 4096 + u] = pack2(q0, q1);
    ((uint32_t*)g_B3)[c * 4096 + u] = pack2(r0, r1);
}

// ======================= persistent eval kernel =======================
__global__ void __launch_bounds__(NTH, 1)
eval_all_kernel(const float* __restrict__ W1,
                const float* __restrict__ b2,
                const float* __restrict__ W3,
                const float* __restrict__ b3,
                float* __restrict__ out) {
    extern __shared__ char smem[];
    const uint32_t sb = smem_u32(smem);
    float*  w1r   = (float*)(smem + SM_W1R);
    float*  c1s   = (float*)(smem + SM_C1);
    float4* bwS   = (float4*)(smem + SM_BW);
    float*  posS  = (float*)(smem + SM_POS);
    float*  dirS  = (float*)(smem + SM_DIR);
    float*  tS    = (float*)(smem + SM_T);
    int*    stS   = (int*)  (smem + SM_ST);
    float*  pS    = (float*)(smem + SM_PS);
    int*    permS = (int*)  (smem + SM_PERM);
    int*    rowOf = (int*)  (smem + SM_ROWOF);
    float*  dfinS = (float*)(smem + SM_DFIN);
    int*    cntS  = (int*)  (smem + SM_CNT);

    const int tid  = threadIdx.x;
    const int lane = tid & 31;
    const int wid  = tid >> 5;     // 0..15
    const int rg   = wid >> 2;     // row block 0..3 (spread across SMSPs!)
    const int cg   = wid & 3;      // col group: cols [cg*64, cg*64+64)
    const int grp  = lane >> 3;    // ldmatrix quad
    const float b3v = b3[0];

    // ---- stage constants ----
    if (tid < 256) {
        w1r[tid]       = W1[tid];
        w1r[256 + tid] = W1[256 + tid];
        w1r[512 + tid] = W1[512 + tid];
        c1s[tid] = g_c1[tid];
    }
    if (tid < 128) {
        float4 bw;
        bw.x = b2[2 * tid]; bw.y = b2[2 * tid + 1];
        bw.z = W3[(2 * tid) * 4]; bw.w = W3[(2 * tid + 1) * 4];
        bwS[tid] = bw;
    }
    // ---- ray init ----
    if (tid < RAYS) {
        int rgid = blockIdx.x * RAYS + tid;
        int view = rgid >> 14;
        int p = rgid & 16383;
        int i = p >> 7, j = p & 127;
        float u = (i + 0.5f) * (1.0f / 128.0f) - 0.5f;
        float v = 0.5f - (j + 0.5f) * (1.0f / 128.0f);
        float dx = u, dy = v, dz = -1.0f;
        float inv = 1.0f / sqrtf(dx * dx + dy * dy + dz * dz);
        dx *= inv; dy *= inv; dz *= inv;
        float s = view ? 0.5f : -0.5f;
        const float c = COS30;
        float rx = c * dx + s * dz;
        float ry = dy;
        float rz = -s * dx + c * dz;
        posS[tid * 3 + 0] = 2.2f * s + 2.2f * rx;
        posS[tid * 3 + 1] = 2.2f * ry;
        posS[tid * 3 + 2] = 2.2f * c + 2.2f * rz;
        dirS[tid * 3 + 0] = rx;
        dirS[tid * 3 + 1] = ry;
        dirS[tid * 3 + 2] = rz;
        tS[tid] = 0.0f;
        stS[tid] = 1;
    }
    __syncthreads();

    // per-thread invariant ldmatrix offsets
    const uint32_t aOff = (uint32_t)((rg * 2 + (grp & 1)) * 128 + (lane & 7) * 16 + (grp >> 1) * 1024);
    const uint32_t bOff = (uint32_t)((cg * 8 + (grp & 1)) * 128 + (lane & 7) * 16 + (grp >> 1) * 4096);

    // ================= 7 sequential SDF evals =================
    for (int e = 0; e < 7; e++) {
        // ---- compaction: rays needing this eval ----
        bool flag = false;
        unsigned bm = 0;
        if (tid < RAYS) {
            permS[tid] = 0;                       // pad default (ray 0)
            int st = stS[tid];
            flag = (e < 6) ? (st == 1) : (st != 0);
            bm = __ballot_sync(0xFFFFFFFFu, flag);
            if (lane == 0) cntS[wid] = __popc(bm);
        }
        __syncthreads();
        if (tid < RAYS && flag) {
            int base = (wid == 1) ? cntS[0] : 0;
            int idx = base + __popc(bm & ((1u << lane) - 1u));
            permS[idx] = tid;
            rowOf[tid] = idx;
        }
        if (tid == 0) cntS[2] = cntS[0] + cntS[1];
        __syncthreads();
        const int n = cntS[2];
        const int nblk = (n + 15) >> 4;

        if (nblk == 0 && e < 6) continue;        // uniform: nothing moves

        if (nblk > 0) {
            // ---- prefetch B chunk 0 (3 planes) into buf 0 ----
            {
                uint32_t d = sb + SM_B;
#pragma unroll
                for (int t = 0; t < 2; t++) {
                    int i = tid + t * 512;
                    CP16(d + (uint32_t)(i * 16),          &g_B1[0][i]);
                    CP16(d + 16384u + (uint32_t)(i * 16), &g_B2[0][i]);
                    CP16(d + 32768u + (uint32_t)(i * 16), &g_B3[0][i]);
                }
                CP_COMMIT();
            }

            // ---- GEMM1 on compacted rows ----
            {
                const int row = tid >> 3;         // 8 threads per row
                const int kq  = tid & 7;          // k in [kq*32, kq*32+32)
                if (row < nblk * 16) {
                    const int ray = permS[row];
                    const float px = posS[ray * 3 + 0];
                    const float py = posS[ray * 3 + 1];
                    const float pz = posS[ray * 3 + 2];
                    uint32_t* a1 = (uint32_t*)(smem + SM_A1);
                    uint32_t* a2 = (uint32_t*)(smem + SM_A2);
                    uint32_t* a3 = (uint32_t*)(smem + SM_A3);
#pragma unroll 4
                    for (int j = 0; j < 16; j++) {
                        int k0 = kq * 32 + 2 * j;
                        float2 wx = *(const float2*)&w1r[k0];
                        float2 wy = *(const float2*)&w1r[256 + k0];
                        float2 wz = *(const float2*)&w1r[512 + k0];
                        float2 cc = *(const float2*)&c1s[k0];
                        float h0 = fmaxf(fmaf(px, wx.x, fmaf(py, wy.x, fmaf(pz, wz.x, cc.x))), 0.0f);
                        float h1 = fmaxf(fmaf(px, wx.y, fmaf(py, wy.y, fmaf(pz, wz.y, cc.y))), 0.0f);
                        __nv_bfloat16 p0, q0, r0, p1, q1, r1;
                        split3(h0, p0, q0, r0);
                        split3(h1, p1, q1, r1);
                        int u = ((k0 >> 3) * 8 + (row >> 3)) * 32 + (row & 7) * 4 + ((k0 & 7) >> 1);
                        a1[u] = pack2(p0, p1);
                        a2[u] = pack2(q0, q1);
                        a3[u] = pack2(r0, r1);
                    }
                }
            }

            // ---- GEMM2 k-loop: 8 chunks of K=32, double-buffered, 6-term split ----
            float acc[8][4];
#pragma unroll
            for (int i = 0; i < 8; i++)
#pragma unroll
                for (int j = 0; j < 4; j++) acc[i][j] = 0.0f;

            const bool doMMA = (rg < nblk);
            for (int c = 0; c < 8; c++) {
                CP_WAIT0();
                __syncthreads();   // chunk c visible; A visible (c==0); buf (c+1)&1 free

                if (c < 7) {
                    uint32_t d = sb + SM_B + (uint32_t)(((c + 1) & 1) * 49152);
#pragma unroll
                    for (int t = 0; t < 2; t++) {
                        int i = tid + t * 512;
                        CP16(d + (uint32_t)(i * 16),          &g_B1[c + 1][i]);
                        CP16(d + 16384u + (uint32_t)(i * 16), &g_B2[c + 1][i]);
                        CP16(d + 32768u + (uint32_t)(i * 16), &g_B3[c + 1][i]);
                    }
                    CP_COMMIT();
                }

                if (doMMA) {
                    const uint32_t bufb = sb + SM_B + (uint32_t)((c & 1) * 49152);
                    const uint32_t aCh  = sb + (uint32_t)(c * 4096);
#pragma unroll
                    for (int s = 0; s < 2; s++) {
                        uint32_t a1f[4], a2f[4], a3f[4];
                        LDSM4(a1f, aCh + SM_A1 + (uint32_t)(s * 2048) + aOff);
                        LDSM4(a2f, aCh + SM_A2 + (uint32_t)(s * 2048) + aOff);
                        LDSM4(a3f, aCh + SM_A3 + (uint32_t)(s * 2048) + aOff);
                        const uint32_t bB = bufb + (uint32_t)(s * 8192) + bOff;
#pragma unroll
                        for (int p = 0; p < 4; p++) {
                            uint32_t b1f[4], b2f[4], b3f[4];
                            LDSM4(b1f, bB + (uint32_t)(p * 256));
                            LDSM4(b2f, bB + 16384u + (uint32_t)(p * 256));
                            LDSM4(b3f, bB + 32768u + (uint32_t)(p * 256));
                            float* c0 = acc[p * 2 + 0];
                            float* c1 = acc[p * 2 + 1];
                            MMA16816(c0, a1f, b1f[0], b1f[2]);   // a1*b1
                            MMA16816(c1, a1f, b1f[1], b1f[3]);
                            MMA16816(c0, a1f, b2f[0], b2f[2]);   // a1*b2
                            MMA16816(c1, a1f, b2f[1], b2f[3]);
                            MMA16816(c0, a2f, b1f[0], b1f[2]);   // a2*b1
                            MMA16816(c1, a2f, b1f[1], b1f[3]);
                            MMA16816(c0, a2f, b2f[0], b2f[2]);   // a2*b2
                            MMA16816(c1, a2f, b2f[1], b2f[3]);
                            MMA16816(c0, a1f, b3f[0], b3f[2]);   // a1*b3
                            MMA16816(c1, a1f, b3f[1], b3f[3]);
                            MMA16816(c0, a3f, b1f[0], b1f[2]);   // a3*b1
                            MMA16816(c1, a3f, b1f[1], b1f[3]);
                        }
                    }
                }
            }

            // ---- epilogue: h2 = relu(acc + b2); partial p = h2 . w3 ----
            if (doMMA) {
                float p0 = 0.0f, p1 = 0.0f;   // rows rg*16+(lane>>2) and +8
#pragma unroll
                for (int nt = 0; nt < 8; nt++) {
                    int n0 = cg * 64 + nt * 8 + (lane & 3) * 2;
                    float4 bw = bwS[n0 >> 1];
                    p0 += fmaxf(acc[nt][0] + bw.x, 0.0f) * bw.z
                        + fmaxf(acc[nt][1] + bw.y, 0.0f) * bw.w;
                    p1 += fmaxf(acc[nt][2] + bw.x, 0.0f) * bw.z
                        + fmaxf(acc[nt][3] + bw.y, 0.0f) * bw.w;
                }
                p0 += __shfl_xor_sync(0xFFFFFFFFu, p0, 1);
                p0 += __shfl_xor_sync(0xFFFFFFFFu, p0, 2);
                p1 += __shfl_xor_sync(0xFFFFFFFFu, p1, 1);
                p1 += __shfl_xor_sync(0xFFFFFFFFu, p1, 2);
                if ((lane & 3) == 0) {
                    int r = rg * 16 + (lane >> 2);
                    pS[cg * 64 + r]     = p0;
                    pS[cg * 64 + r + 8] = p1;
                }
            }
            __syncthreads();
        }

        // ---- per-ray trace update / final output ----
        if (tid < RAYS) {
            int st = stS[tid];
            if (e < 6) {
                if (st == 1) {
                    int row = rowOf[tid];
                    float p = pS[row] + pS[64 + row] + pS[128 + row] + pS[192 + row];
                    float px = posS[tid * 3 + 0];
                    float py = posS[tid * 3 + 1];
                    float pz = posS[tid * 3 + 2];
                    float d = sqrtf(px * px + py * py + pz * pz) - SPHERE_R + (p + b3v);
                    if (fabsf(d) < EPS) {
                        stS[tid] = 0;           // hit: pos frozen, final d known
                        dfinS[tid] = d;
                    } else {
                        float adv = SCALE_TR * d;
                        posS[tid * 3 + 0] = fmaf(adv, dirS[tid * 3 + 0], px);
                        posS[tid * 3 + 1] = fmaf(adv, dirS[tid * 3 + 1], py);
                        posS[tid * 3 + 2] = fmaf(adv, dirS[tid * 3 + 2], pz);
                        float tt = tS[tid] + adv;
                        tS[tid] = tt;
                        if (tt >= MAX_RAY) stS[tid] = 2;   // frozen, needs final eval
                    }
                }
            } else {
                float d;
                if (st == 0) {
                    d = dfinS[tid];
                } else {
                    int row = rowOf[tid];
                    float p = pS[row] + pS[64 + row] + pS[128 + row] + pS[192 + row];
                    float px = posS[tid * 3 + 0];
                    float py = posS[tid * 3 + 1];
                    float pz = posS[tid * 3 + 2];
                    d = sqrtf(px * px + py * py + pz * pz) - SPHERE_R + (p + b3v);
                }
                bool hit = fabsf(d) < EPS;
                int ray = blockIdx.x * RAYS + tid;
                out[ray * 3 + 0] = hit ? posS[tid * 3 + 0] : 0.0f;
                out[ray * 3 + 1] = hit ? posS[tid * 3 + 1] : 0.0f;
                out[ray * 3 + 2] = hit ? posS[tid * 3 + 2] : 0.0f;
            }
        }
        __syncthreads();
    }
}

// ======================= launch =======================
extern "C" void kernel_launch(void* const* d_in, const int* in_sizes, int n_in,
                              void* d_out, int out_size) {
    const float* lat_geo = (const float*)d_in[0];
    const float* lat_exp = (const float*)d_in[1];
    const float* lat_app = (const float*)d_in[2];
    const float* W1      = (const float*)d_in[3];
    const float* b1      = (const float*)d_in[4];
    const float* W2      = (const float*)d_in[5];
    const float* b2      = (const float*)d_in[6];
    const float* W3      = (const float*)d_in[7];
    const float* b3      = (const float*)d_in[8];
    float* out = (float*)d_out;

    cudaFuncSetAttribute(eval_all_kernel,
                         cudaFuncAttributeMaxDynamicSharedMemorySize, SMEM_TOTAL);

    prep_c1_kernel<<<1, 1024>>>(lat_geo, lat_exp, lat_app, W1, b1);
    prep_w2_kernel<<<128, 256>>>(W2);
    eval_all_kernel<<<NBLOCKS, NTH, SMEM_TOTAL>>>(W1, b2, W3, b3, out);
}